// round 5
// baseline (speedup 1.0000x reference)
#include <cuda_runtime.h>
#include <cstdint>
#include <cstddef>

#define N1 131072
#define N2 65536
#define N3 32768
#define NE 1048576
#define NK 25
#define NB 64
#define EPSR 1e-15f

// ---------------- scratch (device globals; no allocation) ----------------
__device__ float g_h1[(size_t)N1 * 32];     // S accumulator (k=0..24, cnt at 25) -> h1 in place
__device__ float g_h2in[(size_t)N2 * 32];
__device__ float g_pos2[(size_t)N2 * 2];
__device__ float g_Y2[(size_t)N2 * 1600];
__device__ float g_agg2[(size_t)N2 * 64];
__device__ float g_cnt2[N2];
__device__ float g_h3in[(size_t)N3 * 64];
__device__ float g_pos3[(size_t)N3 * 2];
__device__ float g_Y3[(size_t)N3 * 1600];
__device__ float g_agg3[(size_t)N3 * 64];
__device__ float g_cnt3[N3];
__device__ unsigned g_maxbits[2];
__device__ float g_pooled[NB * 64];
// sort scratch
__device__ unsigned g_hist[N2];
__device__ unsigned g_offs[N2];
__device__ int g_ssort[NE];
__device__ int g_dsort[NE];

// ---------------- tf32 helpers (gemmY) ----------------
__device__ __forceinline__ uint32_t f2tf32(float x) {
    uint32_t r;
    asm("cvt.rna.tf32.f32 %0, %1;" : "=r"(r) : "f"(x));
    return r;
}

#define MMA_TF32(c, a0, a1, a2, a3, b0, b1)                                          \
    asm volatile(                                                                    \
        "mma.sync.aligned.m16n8k8.row.col.f32.tf32.tf32.f32 "                        \
        "{%0,%1,%2,%3},{%4,%5,%6,%7},{%8,%9},{%0,%1,%2,%3};"                         \
        : "+f"(c[0]), "+f"(c[1]), "+f"(c[2]), "+f"(c[3])                             \
        : "r"(a0), "r"(a1), "r"(a2), "r"(a3), "r"(b0), "r"(b1));

// ---------------- bf16 helpers (kedgeY) ----------------
// pack two floats as bf16x2: lo -> bits[15:0], hi -> bits[31:16]
__device__ __forceinline__ unsigned pk(float lo, float hi) {
    unsigned r;
    asm("cvt.rn.bf16x2.f32 %0, %1, %2;" : "=r"(r) : "f"(hi), "f"(lo));
    return r;
}
__device__ __forceinline__ float bl(unsigned p) { return __uint_as_float(p << 16); }
__device__ __forceinline__ float bh(unsigned p) { return __uint_as_float(p & 0xffff0000u); }

#define MMA_BF16(c, a, bb0, bb1)                                                     \
    asm volatile(                                                                    \
        "mma.sync.aligned.m16n8k16.row.col.f32.bf16.bf16.f32 "                       \
        "{%0,%1,%2,%3},{%4,%5,%6,%7},{%8,%9},{%0,%1,%2,%3};"                         \
        : "+f"(c[0]), "+f"(c[1]), "+f"(c[2]), "+f"(c[3])                             \
        : "r"(a[0]), "r"(a[1]), "r"(a[2]), "r"(a[3]), "r"(bb0), "r"(bb1));

// ---------------- counting sort by src>>1 ----------------
__global__ void khist(const int* __restrict__ ei) {
    int e = blockIdx.x * blockDim.x + threadIdx.x;
    if (e >= NE) return;
    atomicAdd(&g_hist[ei[e] >> 1], 1u);
}

__global__ void kscan() {  // one block, 1024 threads, 64 bins each
    __shared__ unsigned sdata[1024];
    int t = threadIdx.x;
    int base = t * 64;
    unsigned s = 0;
#pragma unroll
    for (int i = 0; i < 64; i++) s += g_hist[base + i];
    sdata[t] = s;
    __syncthreads();
    for (int o = 1; o < 1024; o <<= 1) {
        unsigned v = (t >= o) ? sdata[t - o] : 0u;
        __syncthreads();
        sdata[t] += v;
        __syncthreads();
    }
    unsigned run = sdata[t] - s;  // exclusive prefix
#pragma unroll
    for (int i = 0; i < 64; i++) {
        unsigned h = g_hist[base + i];
        g_offs[base + i] = run;
        run += h;
    }
}

__global__ void kscatter(const int* __restrict__ ei) {
    int e = blockIdx.x * blockDim.x + threadIdx.x;
    if (e >= NE) return;
    int s = ei[e], d = ei[NE + e];
    unsigned p = atomicAdd(&g_offs[s >> 1], 1u);
    g_ssort[p] = s;
    g_dsort[p] = d;
}

// ---------------- pooled positions (pure function of pos) ----------------
__global__ void kpoolpos(const float* __restrict__ pos) {
    int n = blockIdx.x * blockDim.x + threadIdx.x;
    if (n >= N2) return;
    float2 a = *(const float2*)(pos + 4 * n);
    float2 b = *(const float2*)(pos + 4 * n + 2);
    float2 p2 = make_float2(0.5f * (a.x + b.x), 0.5f * (a.y + b.y));
    *(float2*)(g_pos2 + 2 * n) = p2;
    if (n < N3) {
        float2 c = *(const float2*)(pos + 8 * n);
        float2 d = *(const float2*)(pos + 8 * n + 2);
        float2 e = *(const float2*)(pos + 8 * n + 4);
        float2 f = *(const float2*)(pos + 8 * n + 6);
        *(float2*)(g_pos3 + 2 * n) =
            make_float2(0.25f * (c.x + d.x + e.x + f.x), 0.25f * (c.y + d.y + e.y + f.y));
    }
}

// ---------------- fused max |pos[dst]-pos[src]| for both pooled levels ----------------
__global__ void kmaxcart2() {
    int i = blockIdx.x * blockDim.x + threadIdx.x;
    int stride = gridDim.x * blockDim.x;
    float m2 = 0.f, m3 = 0.f;
    for (int e = i; e < NE; e += stride) {
        int s = g_ssort[e], d = g_dsort[e];
        int s2 = s >> 1, d2 = d >> 1, s3 = s >> 2, d3 = d >> 2;
        m2 = fmaxf(m2, fmaxf(fabsf(g_pos2[2 * d2] - g_pos2[2 * s2]),
                             fabsf(g_pos2[2 * d2 + 1] - g_pos2[2 * s2 + 1])));
        m3 = fmaxf(m3, fmaxf(fabsf(g_pos3[2 * d3] - g_pos3[2 * s3]),
                             fabsf(g_pos3[2 * d3 + 1] - g_pos3[2 * s3 + 1])));
    }
#pragma unroll
    for (int o = 16; o; o >>= 1) {
        m2 = fmaxf(m2, __shfl_xor_sync(0xffffffffu, m2, o));
        m3 = fmaxf(m3, __shfl_xor_sync(0xffffffffu, m3, o));
    }
    if ((threadIdx.x & 31) == 0) {
        atomicMax(&g_maxbits[0], __float_as_uint(m2));
        atomicMax(&g_maxbits[1], __float_as_uint(m3));
    }
}

// ---------------- layer 1 edge kernel: S[d,k] += g_k * x[src], 2 edges/warp ----------------
__global__ void kedge1(const int* __restrict__ ei, const float* __restrict__ ea,
                       const float* __restrict__ x, const float* __restrict__ mu,
                       const float* __restrict__ sigma) {
    __shared__ float sMu[NK * 2], sInv[NK * 2];
    int t = threadIdx.x;
    if (t < NK * 2) { sMu[t] = mu[t]; float s = sigma[t]; sInv[t] = 1.f / (EPSR + s * s); }
    __syncthreads();
    int w = (blockIdx.x * blockDim.x + t) >> 5;
    int lane = t & 31;
    int e0 = 2 * w;
    if (e0 >= NE) return;
    float muX = 0.f, muY = 0.f, ivX = 0.f, ivY = 0.f;
    if (lane < NK) { muX = sMu[2 * lane]; muY = sMu[2 * lane + 1]; ivX = sInv[2 * lane]; ivY = sInv[2 * lane + 1]; }
    int s0 = ei[e0], d0 = ei[NE + e0];
    int s1 = ei[e0 + 1], d1 = ei[NE + e0 + 1];
    float2 ea0 = *(const float2*)(ea + 2 * e0);
    float2 ea1 = *(const float2*)(ea + 2 * e0 + 2);
    float x0 = __ldg(&x[s0]), x1 = __ldg(&x[s1]);
    bool v0 = (s0 != d0), v1 = (s1 != d1);
    float g0 = 0.f, g1 = 0.f;
    if (lane < NK) {
        float dx0 = ea0.x - muX, dy0 = ea0.y - muY;
        float dx1 = ea1.x - muX, dy1 = ea1.y - muY;
        g0 = __expf(-0.5f * (dx0 * dx0 * ivX + dy0 * dy0 * ivY)) * x0;
        g1 = __expf(-0.5f * (dx1 * dx1 * ivX + dy1 * dy1 * ivY)) * x1;
    } else if (lane == NK) {
        g0 = 1.f; g1 = 1.f;
    }
    float a0 = __shfl_sync(0xffffffffu, g0, 2 * lane);
    float b0 = __shfl_sync(0xffffffffu, g0, 2 * lane + 1);
    float a1 = __shfl_sync(0xffffffffu, g1, 2 * lane);
    float b1 = __shfl_sync(0xffffffffu, g1, 2 * lane + 1);
    if (lane < 13) {
        if (v0) atomicAdd((float2*)&g_h1[(size_t)d0 * 32 + 2 * lane], make_float2(a0, b0));
        if (v1) atomicAdd((float2*)&g_h1[(size_t)d1 * 32 + 2 * lane], make_float2(a1, b1));
    }
}

// ---------------- layer 1 node: h = elu(S@W1/cnt + x*root + b) (in place on g_h1) -------------
__global__ void knode1(const float* __restrict__ x, const float* __restrict__ W1,
                       const float* __restrict__ root, const float* __restrict__ b) {
    __shared__ float sW[NK * 32];
    int t = threadIdx.x;
    for (int i = t; i < NK * 32; i += blockDim.x) sW[i] = W1[i];
    __syncthreads();
    int n = (blockIdx.x * blockDim.x + t) >> 5;
    int lane = t & 31;
    if (n >= N1) return;
    float* row = &g_h1[(size_t)n * 32];
    float acc = 0.f;
#pragma unroll
    for (int k = 0; k < NK; k++) acc += row[k] * sW[k * 32 + lane];
    float cnt = row[NK];
    float v = acc / fmaxf(cnt, 1.f) + x[n] * root[lane] + b[lane];
    __syncwarp();
    row[lane] = v > 0.f ? v : __expf(v) - 1.f;
}

__global__ void kpool1() {
    int idx = blockIdx.x * blockDim.x + threadIdx.x;
    if (idx >= N2 * 32) return;
    int n = idx >> 5, c = idx & 31;
    g_h2in[idx] = fmaxf(g_h1[(size_t)(2 * n) * 32 + c], g_h1[(size_t)(2 * n + 1) * 32 + c]);
}

// ---------------- per-node Y precompute: tensor cores (tf32 2-term split) ----------------
template <int CIN>
__global__ void kgemmY(const float* __restrict__ H, const float* __restrict__ W,
                       float* __restrict__ Y) {
    constexpr int CINP = CIN + 1;
    __shared__ float sA[64 * CINP];
    __shared__ float sB[CIN * 68];
    int t = threadIdx.x;  // 128
    int n0 = blockIdx.x * 64;
    for (int i = t; i < 64 * CIN; i += 128) {
        int r = i / CIN, c = i % CIN;
        sA[r * CINP + c] = H[(size_t)(n0 + r) * CIN + c];
    }
    int warp = t >> 5, lane = t & 31, g = lane >> 2, tig = lane & 3;
    int wrow = warp * 16;
    constexpr int KT = CIN / 8;
    for (int kb = 0; kb < NK; kb++) {
        __syncthreads();
        for (int i = t; i < CIN * 64; i += 128) {
            int r = i >> 6, c = i & 63;
            sB[r * 68 + c] = W[((size_t)kb * CIN + r) * 64 + c];
        }
        __syncthreads();
        float acc[8][4] = {};
#pragma unroll
        for (int kt = 0; kt < KT; kt++) {
            float fa0 = sA[(wrow + g) * CINP + kt * 8 + tig];
            float fa1 = sA[(wrow + g + 8) * CINP + kt * 8 + tig];
            float fa2 = sA[(wrow + g) * CINP + kt * 8 + tig + 4];
            float fa3 = sA[(wrow + g + 8) * CINP + kt * 8 + tig + 4];
            uint32_t ah0 = f2tf32(fa0), ah1 = f2tf32(fa1), ah2 = f2tf32(fa2), ah3 = f2tf32(fa3);
            uint32_t al0 = f2tf32(fa0 - __uint_as_float(ah0));
            uint32_t al1 = f2tf32(fa1 - __uint_as_float(ah1));
            uint32_t al2 = f2tf32(fa2 - __uint_as_float(ah2));
            uint32_t al3 = f2tf32(fa3 - __uint_as_float(ah3));
#pragma unroll
            for (int nt = 0; nt < 8; nt++) {
                float fb0 = sB[(kt * 8 + tig) * 68 + nt * 8 + g];
                float fb1 = sB[(kt * 8 + tig + 4) * 68 + nt * 8 + g];
                uint32_t bh0 = f2tf32(fb0), bh1 = f2tf32(fb1);
                uint32_t bl0 = f2tf32(fb0 - __uint_as_float(bh0));
                uint32_t bl1 = f2tf32(fb1 - __uint_as_float(bh1));
                MMA_TF32(acc[nt], ah0, ah1, ah2, ah3, bh0, bh1);
                MMA_TF32(acc[nt], ah0, ah1, ah2, ah3, bl0, bl1);
                MMA_TF32(acc[nt], al0, al1, al2, al3, bh0, bh1);
            }
        }
#pragma unroll
        for (int nt = 0; nt < 8; nt++) {
            size_t base = (size_t)(n0 + wrow + g) * 1600 + kb * 64 + nt * 8 + 2 * tig;
            *(float2*)&Y[base] = make_float2(acc[nt][0], acc[nt][1]);
            *(float2*)&Y[base + (size_t)8 * 1600] = make_float2(acc[nt][2], acc[nt][3]);
        }
    }
}

// ---------------- layers 2/3: warp per SRC node, edge messages via bf16 MMA ----------------
// D[16 edges x 64 ch] = G[16 x 32k] @ Yv[32k x 64], 3-pass bf16 2-term split.
template <int SHIFT>
__global__ void __launch_bounds__(256) kedgeY(
        const float* __restrict__ pos,
        const float* __restrict__ mu, const float* __restrict__ sigma,
        const float* __restrict__ Y, float* __restrict__ agg,
        float* __restrict__ cnt, const unsigned* __restrict__ maxbits,
        int nnodes) {
    __shared__ float sMu[NK * 2], sInv[NK * 2];
    int t = threadIdx.x;
    if (t < NK * 2) { sMu[t] = mu[t]; float sv = sigma[t]; sInv[t] = 0.5f / (EPSR + sv * sv); }
    __syncthreads();
    int s = (blockIdx.x * blockDim.x + t) >> 5;
    int lane = t & 31;
    int gid = lane >> 2, tig = lane & 3;
    if (s >= nnodes) return;
    int start, end;
    if (SHIFT == 1) {
        start = (int)(g_offs[s] - g_hist[s]);
        end = (int)g_offs[s];
    } else {
        start = (int)(g_offs[2 * s] - g_hist[2 * s]);
        end = (int)g_offs[2 * s + 1];
    }
    if (start >= end) return;

    // per-thread gaussian params for its 8 k-slots: slot j -> k = 8*(j>>1) + 2*tig + (j&1)
    float mx[8], my[8], ix[8], iy[8];
#pragma unroll
    for (int j = 0; j < 8; j++) {
        int k = 8 * (j >> 1) + 2 * tig + (j & 1);
        bool ok = k < NK;
        mx[j] = ok ? sMu[2 * k] : 0.f;
        my[j] = ok ? sMu[2 * k + 1] : 0.f;
        ix[j] = ok ? sInv[2 * k] : 0.f;
        iy[j] = ok ? sInv[2 * k + 1] : 0.f;
    }

    // B fragments: Yv as bf16 hi/lo, B[k][c] col-major pairs {2tig,2tig+1} / {+8}
    const float* Yr = Y + (size_t)s * 1600;
    unsigned Bh[2][8][2], Bl[2][8][2];
#pragma unroll
    for (int kt = 0; kt < 2; kt++)
#pragma unroll
        for (int nt = 0; nt < 8; nt++) {
            int c = nt * 8 + gid;
#pragma unroll
            for (int h = 0; h < 2; h++) {
                int k0 = kt * 16 + h * 8 + 2 * tig;
                float f0 = (k0 < NK) ? __ldg(&Yr[k0 * 64 + c]) : 0.f;
                float f1 = (k0 + 1 < NK) ? __ldg(&Yr[(k0 + 1) * 64 + c]) : 0.f;
                unsigned hi = pk(f0, f1);
                Bh[kt][nt][h] = hi;
                Bl[kt][nt][h] = pk(f0 - bl(hi), f1 - bh(hi));
            }
        }

    float2 ps = *(const float2*)(pos + 2 * s);
    float scale = 0.5f / fmaxf(__uint_as_float(*maxbits), 1e-12f);

    for (int eb = start; eb < end; eb += 16) {
        int e0 = eb + gid, e1 = eb + gid + 8;
        int dlo = (e0 < end) ? (__ldg(&g_dsort[e0]) >> SHIFT) : s;
        int dhi = (e1 < end) ? (__ldg(&g_dsort[e1]) >> SHIFT) : s;
        bool vlo = dlo != s, vhi = dhi != s;
        float2 plo = __ldg((const float2*)(pos + 2 * dlo));
        float2 phi = __ldg((const float2*)(pos + 2 * dhi));
        float ulx = (plo.x - ps.x) * scale + 0.5f, uly = (plo.y - ps.y) * scale + 0.5f;
        float uhx = (phi.x - ps.x) * scale + 0.5f, uhy = (phi.y - ps.y) * scale + 0.5f;

        // A fragments: rows gid (lo) / gid+8 (hi); k pairs per slot
        unsigned Ah[2][4], Al[2][4];
#pragma unroll
        for (int kt = 0; kt < 2; kt++) {
#pragma unroll
            for (int h = 0; h < 2; h++) {
                int j0 = (kt * 2 + h) * 2;  // slot for even k, j0+1 for odd k
                float dx0 = ulx - mx[j0], dy0 = uly - my[j0];
                float dx1 = ulx - mx[j0 + 1], dy1 = uly - my[j0 + 1];
                float g0 = vlo ? __expf(-(dx0 * dx0 * ix[j0] + dy0 * dy0 * iy[j0])) : 0.f;
                float g1 = vlo ? __expf(-(dx1 * dx1 * ix[j0 + 1] + dy1 * dy1 * iy[j0 + 1])) : 0.f;
                float ex0 = uhx - mx[j0], ey0 = uhy - my[j0];
                float ex1 = uhx - mx[j0 + 1], ey1 = uhy - my[j0 + 1];
                float g2 = vhi ? __expf(-(ex0 * ex0 * ix[j0] + ey0 * ey0 * iy[j0])) : 0.f;
                float g3 = vhi ? __expf(-(ex1 * ex1 * ix[j0 + 1] + ey1 * ey1 * iy[j0 + 1])) : 0.f;
                unsigned hi0 = pk(g0, g1);
                Ah[kt][h * 2] = hi0;
                Al[kt][h * 2] = pk(g0 - bl(hi0), g1 - bh(hi0));
                unsigned hi1 = pk(g2, g3);
                Ah[kt][h * 2 + 1] = hi1;
                Al[kt][h * 2 + 1] = pk(g2 - bl(hi1), g3 - bh(hi1));
            }
        }
        // NOTE Ah[kt] order must be {a0,a1,a2,a3} = {lo k+0, hi k+0, lo k+8, hi k+8}:
        // h=0 wrote indices 0,1; h=1 wrote 2,3.  (matches layout)

        float acc[8][4];
#pragma unroll
        for (int nt = 0; nt < 8; nt++) {
            acc[nt][0] = acc[nt][1] = acc[nt][2] = acc[nt][3] = 0.f;
        }
#pragma unroll
        for (int nt = 0; nt < 8; nt++)
#pragma unroll
            for (int kt = 0; kt < 2; kt++) {
                MMA_BF16(acc[nt], Ah[kt], Bh[kt][nt][0], Bh[kt][nt][1]);
                MMA_BF16(acc[nt], Ah[kt], Bl[kt][nt][0], Bl[kt][nt][1]);
                MMA_BF16(acc[nt], Al[kt], Bh[kt][nt][0], Bh[kt][nt][1]);
            }
        // scatter: thread holds channels {nt*8+2tig, +1} of rows gid / gid+8
#pragma unroll
        for (int nt = 0; nt < 8; nt++) {
            if (vlo)
                atomicAdd((float2*)&agg[(size_t)dlo * 64 + nt * 8 + 2 * tig],
                          make_float2(acc[nt][0], acc[nt][1]));
            if (vhi)
                atomicAdd((float2*)&agg[(size_t)dhi * 64 + nt * 8 + 2 * tig],
                          make_float2(acc[nt][2], acc[nt][3]));
        }
        if (tig == 0) {
            if (vlo) atomicAdd(&cnt[dlo], 1.f);
            if (vhi) atomicAdd(&cnt[dhi], 1.f);
        }
    }
}

template <int CIN, bool RELU>
__global__ void knode23(const float* __restrict__ hin, const float* __restrict__ root,
                        const float* __restrict__ b, float* __restrict__ agg,
                        const float* __restrict__ cnt, int nrows) {
    int idx = blockIdx.x * blockDim.x + threadIdx.x;
    if (idx >= nrows * 64) return;
    int n = idx >> 6, c = idx & 63;
    float r = b[c];
    const float* hr = hin + (size_t)n * CIN;
#pragma unroll
    for (int i = 0; i < CIN; i++) r += hr[i] * root[i * 64 + c];
    float v = agg[idx] / fmaxf(cnt[n], 1.f) + r;
    agg[idx] = RELU ? fmaxf(v, 0.f) : (v > 0.f ? v : __expf(v) - 1.f);
}

__global__ void kpool2() {
    int idx = blockIdx.x * blockDim.x + threadIdx.x;
    if (idx >= N3 * 64) return;
    int n = idx >> 6, c = idx & 63;
    g_h3in[idx] = fmaxf(g_agg2[(size_t)(2 * n) * 64 + c], g_agg2[(size_t)(2 * n + 1) * 64 + c]);
}

__global__ void kbatchpool() {
    __shared__ float sred[256];
    int b = blockIdx.x, t = threadIdx.x;
    int c = t & 63, part = t >> 6;
    float s = 0.f;
    for (int j = part; j < 512; j += 4) s += g_agg3[(size_t)(b * 512 + j) * 64 + c];
    sred[t] = s;
    __syncthreads();
    if (part == 0)
        g_pooled[b * 64 + c] = (sred[c] + sred[64 + c] + sred[128 + c] + sred[192 + c]) * (1.f / 512.f);
}

__global__ void khead(const float* __restrict__ fw1, const float* __restrict__ fb1,
                      const float* __restrict__ fw2, const float* __restrict__ fb2,
                      float* __restrict__ out) {
    int b = blockIdx.x;
    int t = threadIdx.x;
    __shared__ float sp[64], sz[128], so[10], lse;
    if (t < 64) sp[t] = g_pooled[b * 64 + t];
    __syncthreads();
    float acc = fb1[t];
    for (int i = 0; i < 64; i++) acc += sp[i] * fw1[i * 128 + t];
    sz[t] = acc > 0.f ? acc : expf(acc) - 1.f;
    __syncthreads();
    if (t < 10) {
        float o = fb2[t];
        for (int j = 0; j < 128; j++) o += sz[j] * fw2[j * 10 + t];
        so[t] = o;
    }
    __syncthreads();
    if (t == 0) {
        float m = so[0];
        for (int i = 1; i < 10; i++) m = fmaxf(m, so[i]);
        float s = 0.f;
        for (int i = 0; i < 10; i++) s += expf(so[i] - m);
        lse = m + logf(s);
    }
    __syncthreads();
    if (t < 10) out[b * 10 + t] = so[t] - lse;
}

// ---------------- launch ----------------
extern "C" void kernel_launch(void* const* d_in, const int* in_sizes, int n_in,
                              void* d_out, int out_size) {
    const float* x   = (const float*)d_in[0];
    const int*   ei  = (const int*)d_in[1];
    const float* ea  = (const float*)d_in[2];
    const float* pos = (const float*)d_in[3];
    const float* mu1 = (const float*)d_in[5];
    const float* sg1 = (const float*)d_in[6];
    const float* W1  = (const float*)d_in[7];
    const float* r1  = (const float*)d_in[8];
    const float* b1  = (const float*)d_in[9];
    const float* mu2 = (const float*)d_in[10];
    const float* sg2 = (const float*)d_in[11];
    const float* W2  = (const float*)d_in[12];
    const float* r2  = (const float*)d_in[13];
    const float* b2  = (const float*)d_in[14];
    const float* mu3 = (const float*)d_in[15];
    const float* sg3 = (const float*)d_in[16];
    const float* W3  = (const float*)d_in[17];
    const float* r3  = (const float*)d_in[18];
    const float* b3  = (const float*)d_in[19];
    const float* fw1 = (const float*)d_in[20];
    const float* fb1 = (const float*)d_in[21];
    const float* fw2 = (const float*)d_in[22];
    const float* fb2 = (const float*)d_in[23];
    float* out = (float*)d_out;

    void *p_h1, *p_h2, *p_Y2, *p_a2, *p_c2, *p_h3, *p_Y3, *p_a3, *p_c3, *p_mb, *p_p2, *p_p3, *p_hist;
    cudaGetSymbolAddress(&p_h1, g_h1);
    cudaGetSymbolAddress(&p_h2, g_h2in);
    cudaGetSymbolAddress(&p_Y2, g_Y2);
    cudaGetSymbolAddress(&p_a2, g_agg2);
    cudaGetSymbolAddress(&p_c2, g_cnt2);
    cudaGetSymbolAddress(&p_h3, g_h3in);
    cudaGetSymbolAddress(&p_Y3, g_Y3);
    cudaGetSymbolAddress(&p_a3, g_agg3);
    cudaGetSymbolAddress(&p_c3, g_cnt3);
    cudaGetSymbolAddress(&p_mb, g_maxbits);
    cudaGetSymbolAddress(&p_p2, g_pos2);
    cudaGetSymbolAddress(&p_p3, g_pos3);
    cudaGetSymbolAddress(&p_hist, g_hist);

    cudaMemsetAsync(p_h1, 0, (size_t)N1 * 32 * 4);
    cudaMemsetAsync(p_a2, 0, (size_t)N2 * 64 * 4);
    cudaMemsetAsync(p_c2, 0, (size_t)N2 * 4);
    cudaMemsetAsync(p_a3, 0, (size_t)N3 * 64 * 4);
    cudaMemsetAsync(p_c3, 0, (size_t)N3 * 4);
    cudaMemsetAsync(p_mb, 0, 2 * 4);
    cudaMemsetAsync(p_hist, 0, (size_t)N2 * 4);

    // counting sort of edges by src>>1 (serves layers 2 and 3)
    khist<<<NE / 256, 256>>>(ei);
    kscan<<<1, 1024>>>();
    kscatter<<<NE / 256, 256>>>(ei);

    // pooled positions + fused max-cart (independent of h)
    kpoolpos<<<N2 / 256, 256>>>(pos);
    kmaxcart2<<<1024, 256>>>();

    // layer 1
    kedge1<<<NE * 32 / 2 / 256, 256>>>(ei, ea, x, mu1, sg1);
    knode1<<<N1 * 32 / 256, 256>>>(x, W1, r1, b1);
    kpool1<<<N2 * 32 / 256, 256>>>();

    // layer 2
    kgemmY<32><<<N2 / 64, 128>>>((const float*)p_h2, W2, (float*)p_Y2);
    kedgeY<1><<<N2 * 32 / 256, 256>>>((const float*)p_p2, mu2, sg2,
                                      (const float*)p_Y2, (float*)p_a2, (float*)p_c2,
                                      (const unsigned*)p_mb, N2);
    knode23<32, true><<<N2 * 64 / 256, 256>>>((const float*)p_h2, r2, b2,
                                              (float*)p_a2, (const float*)p_c2, N2);
    kpool2<<<N3 * 64 / 256, 256>>>();

    // layer 3
    kgemmY<64><<<N3 / 64, 128>>>((const float*)p_h3, W3, (float*)p_Y3);
    kedgeY<2><<<N3 * 32 / 256, 256>>>((const float*)p_p3, mu3, sg3,
                                      (const float*)p_Y3, (float*)p_a3, (float*)p_c3,
                                      ((const unsigned*)p_mb) + 1, N3);
    knode23<64, false><<<N3 * 64 / 256, 256>>>((const float*)p_h3, r3, b3,
                                               (float*)p_a3, (const float*)p_c3, N3);

    // readout
    kbatchpool<<<NB, 256>>>();
    khead<<<NB, 128>>>(fw1, fb1, fw2, fb2, out);
}

// round 6
// speedup vs baseline: 1.0007x; 1.0007x over previous
#include <cuda_runtime.h>
#include <cstdint>
#include <cstddef>

#define N1 131072
#define N2 65536
#define N3 32768
#define NE 1048576
#define NK 25
#define NB 64
#define EPSR 1e-15f

// ---------------- scratch (device globals; no allocation) ----------------
__device__ float g_h1[(size_t)N1 * 32];     // S accumulator (k=0..24, cnt at 25)
__device__ float g_h2in[(size_t)N2 * 32];
__device__ float g_pos2[(size_t)N2 * 2];
__device__ float g_Y2[(size_t)N2 * 1600];
__device__ float g_agg2[(size_t)N2 * 64];
__device__ float g_cnt2[N2];
__device__ float g_h3in[(size_t)N3 * 64];
__device__ float g_pos3[(size_t)N3 * 2];
__device__ float g_Y3[(size_t)N3 * 1600];
__device__ float g_agg3[(size_t)N3 * 64];
__device__ float g_cnt3[N3];
__device__ unsigned g_maxbits[2];
__device__ float g_pooled[NB * 64];
// sort scratch
__device__ unsigned g_hist[N2];
__device__ unsigned g_offs[N2];
__device__ int g_ssort[NE];
__device__ int g_dsort[NE];

// ---------------- tf32 helpers (gemmY) ----------------
__device__ __forceinline__ uint32_t f2tf32(float x) {
    uint32_t r;
    asm("cvt.rna.tf32.f32 %0, %1;" : "=r"(r) : "f"(x));
    return r;
}

#define MMA_TF32(c, a0, a1, a2, a3, b0, b1)                                          \
    asm volatile(                                                                    \
        "mma.sync.aligned.m16n8k8.row.col.f32.tf32.tf32.f32 "                        \
        "{%0,%1,%2,%3},{%4,%5,%6,%7},{%8,%9},{%0,%1,%2,%3};"                         \
        : "+f"(c[0]), "+f"(c[1]), "+f"(c[2]), "+f"(c[3])                             \
        : "r"(a0), "r"(a1), "r"(a2), "r"(a3), "r"(b0), "r"(b1));

// ---------------- counting sort by src>>1 ----------------
__global__ void khist(const int* __restrict__ ei) {
    int e = blockIdx.x * blockDim.x + threadIdx.x;
    if (e >= NE) return;
    atomicAdd(&g_hist[ei[e] >> 1], 1u);
}

__global__ void kscan() {  // one block, 1024 threads, 64 bins each
    __shared__ unsigned sdata[1024];
    int t = threadIdx.x;
    int base = t * 64;
    unsigned s = 0;
#pragma unroll
    for (int i = 0; i < 64; i++) s += g_hist[base + i];
    sdata[t] = s;
    __syncthreads();
    for (int o = 1; o < 1024; o <<= 1) {
        unsigned v = (t >= o) ? sdata[t - o] : 0u;
        __syncthreads();
        sdata[t] += v;
        __syncthreads();
    }
    unsigned run = sdata[t] - s;  // exclusive prefix
#pragma unroll
    for (int i = 0; i < 64; i++) {
        unsigned h = g_hist[base + i];
        g_offs[base + i] = run;
        run += h;
    }
}

__global__ void kscatter(const int* __restrict__ ei) {
    int e = blockIdx.x * blockDim.x + threadIdx.x;
    if (e >= NE) return;
    int s = ei[e], d = ei[NE + e];
    unsigned p = atomicAdd(&g_offs[s >> 1], 1u);
    g_ssort[p] = s;
    g_dsort[p] = d;
}

// ---------------- pooled positions (pure function of pos) ----------------
__global__ void kpoolpos(const float* __restrict__ pos) {
    int n = blockIdx.x * blockDim.x + threadIdx.x;
    if (n >= N2) return;
    float2 a = *(const float2*)(pos + 4 * n);
    float2 b = *(const float2*)(pos + 4 * n + 2);
    *(float2*)(g_pos2 + 2 * n) = make_float2(0.5f * (a.x + b.x), 0.5f * (a.y + b.y));
    if (n < N3) {
        float2 c = *(const float2*)(pos + 8 * n);
        float2 d = *(const float2*)(pos + 8 * n + 2);
        float2 e = *(const float2*)(pos + 8 * n + 4);
        float2 f = *(const float2*)(pos + 8 * n + 6);
        *(float2*)(g_pos3 + 2 * n) =
            make_float2(0.25f * (c.x + d.x + e.x + f.x), 0.25f * (c.y + d.y + e.y + f.y));
    }
}

// ---------------- fused max |pos[dst]-pos[src]| for both pooled levels ----------------
__global__ void kmaxcart2() {
    int i = blockIdx.x * blockDim.x + threadIdx.x;
    int stride = gridDim.x * blockDim.x;
    float m2 = 0.f, m3 = 0.f;
    for (int e = i; e < NE; e += stride) {
        int s = g_ssort[e], d = g_dsort[e];
        int s2 = s >> 1, d2 = d >> 1, s3 = s >> 2, d3 = d >> 2;
        m2 = fmaxf(m2, fmaxf(fabsf(g_pos2[2 * d2] - g_pos2[2 * s2]),
                             fabsf(g_pos2[2 * d2 + 1] - g_pos2[2 * s2 + 1])));
        m3 = fmaxf(m3, fmaxf(fabsf(g_pos3[2 * d3] - g_pos3[2 * s3]),
                             fabsf(g_pos3[2 * d3 + 1] - g_pos3[2 * s3 + 1])));
    }
#pragma unroll
    for (int o = 16; o; o >>= 1) {
        m2 = fmaxf(m2, __shfl_xor_sync(0xffffffffu, m2, o));
        m3 = fmaxf(m3, __shfl_xor_sync(0xffffffffu, m3, o));
    }
    if ((threadIdx.x & 31) == 0) {
        atomicMax(&g_maxbits[0], __float_as_uint(m2));
        atomicMax(&g_maxbits[1], __float_as_uint(m3));
    }
}

// ---------------- layer 1 edge kernel: S[d,k] += g_k * x[src], 4 edges/warp ----------------
__global__ void kedge1(const int* __restrict__ ei, const float* __restrict__ ea,
                       const float* __restrict__ x, const float* __restrict__ mu,
                       const float* __restrict__ sigma) {
    __shared__ float sMu[NK * 2], sInv[NK * 2];
    int t = threadIdx.x;
    if (t < NK * 2) { sMu[t] = mu[t]; float s = sigma[t]; sInv[t] = 1.f / (EPSR + s * s); }
    __syncthreads();
    int w = (blockIdx.x * blockDim.x + t) >> 5;
    int lane = t & 31;
    int e0 = 4 * w;
    if (e0 >= NE) return;
    float muX = 0.f, muY = 0.f, ivX = 0.f, ivY = 0.f;
    if (lane < NK) { muX = sMu[2 * lane]; muY = sMu[2 * lane + 1]; ivX = sInv[2 * lane]; ivY = sInv[2 * lane + 1]; }
    int ss[4], dd[4];
    float2 eav[4];
    float xs[4], gg[4];
    bool vv[4];
#pragma unroll
    for (int i = 0; i < 4; i++) {
        ss[i] = ei[e0 + i];
        dd[i] = ei[NE + e0 + i];
        eav[i] = *(const float2*)(ea + 2 * (e0 + i));
        xs[i] = __ldg(&x[ss[i]]);
        vv[i] = (ss[i] != dd[i]);
    }
#pragma unroll
    for (int i = 0; i < 4; i++) {
        gg[i] = 0.f;
        if (lane < NK) {
            float dx = eav[i].x - muX, dy = eav[i].y - muY;
            gg[i] = __expf(-0.5f * (dx * dx * ivX + dy * dy * ivY)) * xs[i];
        } else if (lane == NK) {
            gg[i] = 1.f;
        }
    }
#pragma unroll
    for (int i = 0; i < 4; i++) {
        float a = __shfl_sync(0xffffffffu, gg[i], 2 * lane);
        float b = __shfl_sync(0xffffffffu, gg[i], 2 * lane + 1);
        if (lane < 13 && vv[i])
            atomicAdd((float2*)&g_h1[(size_t)dd[i] * 32 + 2 * lane], make_float2(a, b));
    }
}

// ---------------- fused layer1 node + pool: h2in[n] = max(elu(row(2n)), elu(row(2n+1))) -----
__global__ void knp1(const float* __restrict__ x, const float* __restrict__ W1,
                     const float* __restrict__ root, const float* __restrict__ b) {
    __shared__ float sW[NK * 32];
    int t = threadIdx.x;
    for (int i = t; i < NK * 32; i += blockDim.x) sW[i] = W1[i];
    __syncthreads();
    int n = (blockIdx.x * blockDim.x + t) >> 5;  // pair index
    int lane = t & 31;
    if (n >= N2) return;
    const float* row0 = &g_h1[(size_t)(2 * n) * 32];
    const float* row1 = row0 + 32;
    float acc0 = 0.f, acc1 = 0.f;
#pragma unroll
    for (int k = 0; k < NK; k++) {
        float w = sW[k * 32 + lane];
        acc0 += row0[k] * w;
        acc1 += row1[k] * w;
    }
    float rt = root[lane], bb = b[lane];
    float v0 = acc0 / fmaxf(row0[NK], 1.f) + x[2 * n] * rt + bb;
    float v1 = acc1 / fmaxf(row1[NK], 1.f) + x[2 * n + 1] * rt + bb;
    v0 = v0 > 0.f ? v0 : __expf(v0) - 1.f;
    v1 = v1 > 0.f ? v1 : __expf(v1) - 1.f;
    g_h2in[(size_t)n * 32 + lane] = fmaxf(v0, v1);
}

// ---------------- per-node Y precompute: tensor cores (tf32 2-term split) ----------------
template <int CIN>
__global__ void kgemmY(const float* __restrict__ H, const float* __restrict__ W,
                       float* __restrict__ Y) {
    constexpr int CINP = CIN + 1;
    __shared__ float sA[64 * CINP];
    __shared__ float sB[CIN * 68];
    int t = threadIdx.x;  // 128
    int n0 = blockIdx.x * 64;
    for (int i = t; i < 64 * CIN; i += 128) {
        int r = i / CIN, c = i % CIN;
        sA[r * CINP + c] = H[(size_t)(n0 + r) * CIN + c];
    }
    int warp = t >> 5, lane = t & 31, g = lane >> 2, tig = lane & 3;
    int wrow = warp * 16;
    constexpr int KT = CIN / 8;
    for (int kb = 0; kb < NK; kb++) {
        __syncthreads();
        for (int i = t; i < CIN * 64; i += 128) {
            int r = i >> 6, c = i & 63;
            sB[r * 68 + c] = W[((size_t)kb * CIN + r) * 64 + c];
        }
        __syncthreads();
        float acc[8][4] = {};
#pragma unroll
        for (int kt = 0; kt < KT; kt++) {
            float fa0 = sA[(wrow + g) * CINP + kt * 8 + tig];
            float fa1 = sA[(wrow + g + 8) * CINP + kt * 8 + tig];
            float fa2 = sA[(wrow + g) * CINP + kt * 8 + tig + 4];
            float fa3 = sA[(wrow + g + 8) * CINP + kt * 8 + tig + 4];
            uint32_t ah0 = f2tf32(fa0), ah1 = f2tf32(fa1), ah2 = f2tf32(fa2), ah3 = f2tf32(fa3);
            uint32_t al0 = f2tf32(fa0 - __uint_as_float(ah0));
            uint32_t al1 = f2tf32(fa1 - __uint_as_float(ah1));
            uint32_t al2 = f2tf32(fa2 - __uint_as_float(ah2));
            uint32_t al3 = f2tf32(fa3 - __uint_as_float(ah3));
#pragma unroll
            for (int nt = 0; nt < 8; nt++) {
                float fb0 = sB[(kt * 8 + tig) * 68 + nt * 8 + g];
                float fb1 = sB[(kt * 8 + tig + 4) * 68 + nt * 8 + g];
                uint32_t bh0 = f2tf32(fb0), bh1 = f2tf32(fb1);
                uint32_t bl0 = f2tf32(fb0 - __uint_as_float(bh0));
                uint32_t bl1 = f2tf32(fb1 - __uint_as_float(bh1));
                MMA_TF32(acc[nt], ah0, ah1, ah2, ah3, bh0, bh1);
                MMA_TF32(acc[nt], ah0, ah1, ah2, ah3, bl0, bl1);
                MMA_TF32(acc[nt], al0, al1, al2, al3, bh0, bh1);
            }
        }
#pragma unroll
        for (int nt = 0; nt < 8; nt++) {
            size_t base = (size_t)(n0 + wrow + g) * 1600 + kb * 64 + nt * 8 + 2 * tig;
            *(float2*)&Y[base] = make_float2(acc[nt][0], acc[nt][1]);
            *(float2*)&Y[base + (size_t)8 * 1600] = make_float2(acc[nt][2], acc[nt][3]);
        }
    }
}

// ---------------- layers 2/3: warp per SRC node, Y row in registers, 4-edge unroll ----------
template <int SHIFT>
__global__ void __launch_bounds__(256) kedgeY(
        const float* __restrict__ pos,
        const float* __restrict__ mu, const float* __restrict__ sigma,
        const float* __restrict__ Y, float* __restrict__ agg,
        float* __restrict__ cnt, const unsigned* __restrict__ maxbits,
        int nnodes) {
    __shared__ float sMu[NK * 2], sInv[NK * 2];
    int t = threadIdx.x;
    if (t < NK * 2) { sMu[t] = mu[t]; float sv = sigma[t]; sInv[t] = 1.f / (EPSR + sv * sv); }
    __syncthreads();
    int s = (blockIdx.x * blockDim.x + t) >> 5;
    int lane = t & 31;
    if (s >= nnodes) return;
    int start, end;
    if (SHIFT == 1) {
        start = (int)(g_offs[s] - g_hist[s]);
        end = (int)g_offs[s];
    } else {
        start = (int)(g_offs[2 * s] - g_hist[2 * s]);
        end = (int)g_offs[2 * s + 1];
    }
    if (start >= end) return;
    float2 Yv[NK];
    const float* Yr = Y + (size_t)s * 1600;
#pragma unroll
    for (int k = 0; k < NK; k++) Yv[k] = __ldg((const float2*)(Yr + k * 64 + 2 * lane));
    float2 ps = *(const float2*)(pos + 2 * s);
    float scale = 0.5f / fmaxf(__uint_as_float(*maxbits), 1e-12f);
    float muX = 0.f, muY = 0.f, ivX = 0.f, ivY = 0.f;
    if (lane < NK) { muX = sMu[2 * lane]; muY = sMu[2 * lane + 1]; ivX = sInv[2 * lane]; ivY = sInv[2 * lane + 1]; }

    for (int e = start; e < end; e += 4) {
        int dd[4];
        bool vv[4];
        float gg[4];
#pragma unroll
        for (int i = 0; i < 4; i++) {
            int ee = e + i;
            dd[i] = (ee < end) ? (__ldg(&g_dsort[ee]) >> SHIFT) : s;
            vv[i] = dd[i] != s;
        }
#pragma unroll
        for (int i = 0; i < 4; i++) {
            float2 pd = __ldg((const float2*)(pos + 2 * dd[i]));
            gg[i] = 0.f;
            if (lane < NK && vv[i]) {
                float px = (pd.x - ps.x) * scale + 0.5f - muX;
                float py = (pd.y - ps.y) * scale + 0.5f - muY;
                gg[i] = __expf(-0.5f * (px * px * ivX + py * py * ivY));
            }
        }
        float ax[4] = {}, ay[4] = {};
#pragma unroll
        for (int k = 0; k < NK; k++) {
#pragma unroll
            for (int i = 0; i < 4; i++) {
                float gk = __shfl_sync(0xffffffffu, gg[i], k);
                ax[i] += gk * Yv[k].x;
                ay[i] += gk * Yv[k].y;
            }
        }
#pragma unroll
        for (int i = 0; i < 4; i++) {
            if (vv[i]) {
                atomicAdd((float2*)&agg[(size_t)dd[i] * 64 + 2 * lane], make_float2(ax[i], ay[i]));
                if (lane == 0) atomicAdd(&cnt[dd[i]], 1.f);
            }
        }
    }
}

// ---------------- fused layer2 node + pool: h3in = max over pair of relu(node out) ----------
__global__ void knp2(const float* __restrict__ root, const float* __restrict__ b) {
    int idx = blockIdx.x * blockDim.x + threadIdx.x;
    if (idx >= N3 * 64) return;
    int n = idx >> 6, c = idx & 63;
    float r0 = b[c], r1 = r0;
    const float* h0 = &g_h2in[(size_t)(2 * n) * 32];
    const float* h1 = h0 + 32;
#pragma unroll
    for (int i = 0; i < 32; i++) {
        float w = root[i * 64 + c];
        r0 += h0[i] * w;
        r1 += h1[i] * w;
    }
    float v0 = g_agg2[(size_t)(2 * n) * 64 + c] / fmaxf(g_cnt2[2 * n], 1.f) + r0;
    float v1 = g_agg2[(size_t)(2 * n + 1) * 64 + c] / fmaxf(g_cnt2[2 * n + 1], 1.f) + r1;
    g_h3in[idx] = fmaxf(fmaxf(v0, 0.f), fmaxf(v1, 0.f));
}

// ---------------- layer 3 node (ELU, in place on agg3) ----------------
__global__ void knode3(const float* __restrict__ root, const float* __restrict__ b) {
    int idx = blockIdx.x * blockDim.x + threadIdx.x;
    if (idx >= N3 * 64) return;
    int n = idx >> 6, c = idx & 63;
    float r = b[c];
    const float* hr = &g_h3in[(size_t)n * 64];
#pragma unroll
    for (int i = 0; i < 64; i++) r += hr[i] * root[i * 64 + c];
    float v = g_agg3[idx] / fmaxf(g_cnt3[n], 1.f) + r;
    g_agg3[idx] = v > 0.f ? v : __expf(v) - 1.f;
}

__global__ void kbatchpool() {
    __shared__ float sred[256];
    int b = blockIdx.x, t = threadIdx.x;
    int c = t & 63, part = t >> 6;
    float s = 0.f;
    for (int j = part; j < 512; j += 4) s += g_agg3[(size_t)(b * 512 + j) * 64 + c];
    sred[t] = s;
    __syncthreads();
    if (part == 0)
        g_pooled[b * 64 + c] = (sred[c] + sred[64 + c] + sred[128 + c] + sred[192 + c]) * (1.f / 512.f);
}

__global__ void khead(const float* __restrict__ fw1, const float* __restrict__ fb1,
                      const float* __restrict__ fw2, const float* __restrict__ fb2,
                      float* __restrict__ out) {
    int b = blockIdx.x;
    int t = threadIdx.x;
    __shared__ float sp[64], sz[128], so[10], lse;
    if (t < 64) sp[t] = g_pooled[b * 64 + t];
    __syncthreads();
    float acc = fb1[t];
    for (int i = 0; i < 64; i++) acc += sp[i] * fw1[i * 128 + t];
    sz[t] = acc > 0.f ? acc : expf(acc) - 1.f;
    __syncthreads();
    if (t < 10) {
        float o = fb2[t];
        for (int j = 0; j < 128; j++) o += sz[j] * fw2[j * 10 + t];
        so[t] = o;
    }
    __syncthreads();
    if (t == 0) {
        float m = so[0];
        for (int i = 1; i < 10; i++) m = fmaxf(m, so[i]);
        float s = 0.f;
        for (int i = 0; i < 10; i++) s += expf(so[i] - m);
        lse = m + logf(s);
    }
    __syncthreads();
    if (t < 10) out[b * 10 + t] = so[t] - lse;
}

// ---------------- launch ----------------
extern "C" void kernel_launch(void* const* d_in, const int* in_sizes, int n_in,
                              void* d_out, int out_size) {
    const float* x   = (const float*)d_in[0];
    const int*   ei  = (const int*)d_in[1];
    const float* ea  = (const float*)d_in[2];
    const float* pos = (const float*)d_in[3];
    const float* mu1 = (const float*)d_in[5];
    const float* sg1 = (const float*)d_in[6];
    const float* W1  = (const float*)d_in[7];
    const float* r1  = (const float*)d_in[8];
    const float* b1  = (const float*)d_in[9];
    const float* mu2 = (const float*)d_in[10];
    const float* sg2 = (const float*)d_in[11];
    const float* W2  = (const float*)d_in[12];
    const float* r2  = (const float*)d_in[13];
    const float* b2  = (const float*)d_in[14];
    const float* mu3 = (const float*)d_in[15];
    const float* sg3 = (const float*)d_in[16];
    const float* W3  = (const float*)d_in[17];
    const float* r3  = (const float*)d_in[18];
    const float* b3  = (const float*)d_in[19];
    const float* fw1 = (const float*)d_in[20];
    const float* fb1 = (const float*)d_in[21];
    const float* fw2 = (const float*)d_in[22];
    const float* fb2 = (const float*)d_in[23];
    float* out = (float*)d_out;

    void *p_h1, *p_h2, *p_Y2, *p_a2, *p_c2, *p_h3, *p_Y3, *p_a3, *p_c3, *p_mb, *p_p2, *p_p3, *p_hist;
    cudaGetSymbolAddress(&p_h1, g_h1);
    cudaGetSymbolAddress(&p_h2, g_h2in);
    cudaGetSymbolAddress(&p_Y2, g_Y2);
    cudaGetSymbolAddress(&p_a2, g_agg2);
    cudaGetSymbolAddress(&p_c2, g_cnt2);
    cudaGetSymbolAddress(&p_h3, g_h3in);
    cudaGetSymbolAddress(&p_Y3, g_Y3);
    cudaGetSymbolAddress(&p_a3, g_agg3);
    cudaGetSymbolAddress(&p_c3, g_cnt3);
    cudaGetSymbolAddress(&p_mb, g_maxbits);
    cudaGetSymbolAddress(&p_p2, g_pos2);
    cudaGetSymbolAddress(&p_p3, g_pos3);
    cudaGetSymbolAddress(&p_hist, g_hist);

    cudaMemsetAsync(p_h1, 0, (size_t)N1 * 32 * 4);
    cudaMemsetAsync(p_a2, 0, (size_t)N2 * 64 * 4);
    cudaMemsetAsync(p_c2, 0, (size_t)N2 * 4);
    cudaMemsetAsync(p_a3, 0, (size_t)N3 * 64 * 4);
    cudaMemsetAsync(p_c3, 0, (size_t)N3 * 4);
    cudaMemsetAsync(p_mb, 0, 2 * 4);
    cudaMemsetAsync(p_hist, 0, (size_t)N2 * 4);

    // counting sort of edges by src>>1 (serves layers 2 and 3)
    khist<<<NE / 256, 256>>>(ei);
    kscan<<<1, 1024>>>();
    kscatter<<<NE / 256, 256>>>(ei);

    // pooled positions + fused max-cart (independent of h)
    kpoolpos<<<N2 / 256, 256>>>(pos);
    kmaxcart2<<<1024, 256>>>();

    // layer 1
    kedge1<<<NE * 32 / 4 / 256, 256>>>(ei, ea, x, mu1, sg1);
    knp1<<<N2 * 32 / 256, 256>>>(x, W1, r1, b1);

    // layer 2
    kgemmY<32><<<N2 / 64, 128>>>((const float*)p_h2, W2, (float*)p_Y2);
    kedgeY<1><<<N2 * 32 / 256, 256>>>((const float*)p_p2, mu2, sg2,
                                      (const float*)p_Y2, (float*)p_a2, (float*)p_c2,
                                      (const unsigned*)p_mb, N2);
    knp2<<<N3 * 64 / 256, 256>>>(r2, b2);

    // layer 3
    kgemmY<64><<<N3 / 64, 128>>>((const float*)p_h3, W3, (float*)p_Y3);
    kedgeY<2><<<N3 * 32 / 256, 256>>>((const float*)p_p3, mu3, sg3,
                                      (const float*)p_Y3, (float*)p_a3, (float*)p_c3,
                                      ((const unsigned*)p_mb) + 1, N3);
    knode3<<<N3 * 64 / 256, 256>>>(r3, b3);

    // readout
    kbatchpool<<<NB, 256>>>();
    khead<<<NB, 128>>>(fw1, fb1, fw2, fb2, out);
}

// round 7
// speedup vs baseline: 1.1924x; 1.1916x over previous
#include <cuda_runtime.h>
#include <cstdint>
#include <cstddef>

#define N1 131072
#define N2 65536
#define N3 32768
#define NE 1048576
#define NK 25
#define NB 64
#define EPSR 1e-15f

// ---------------- scratch (device globals; no allocation) ----------------
__device__ float g_h1[(size_t)N1 * 32];     // S accumulator (k=0..24, cnt at 25)
__device__ float g_h2in[(size_t)N2 * 32];
__device__ float g_pos2[(size_t)N2 * 2];
__device__ float g_Y2[(size_t)N2 * 1600];
__device__ float g_agg2[(size_t)N2 * 64];
__device__ float g_cnt2[N2];
__device__ float g_h3in[(size_t)N3 * 64];
__device__ float g_pos3[(size_t)N3 * 2];
__device__ float g_Y3[(size_t)N3 * 1600];
__device__ float g_agg3[(size_t)N3 * 64];
__device__ float g_cnt3[N3];
__device__ unsigned g_maxbits[2];
__device__ float g_pooled[NB * 64];
// sort scratch
__device__ unsigned g_hist[N2];
__device__ unsigned g_offs[N2];
__device__ int g_ssort[NE];
__device__ int g_dsort[NE];

// ---------------- tf32 helpers (gemmY) ----------------
__device__ __forceinline__ uint32_t f2tf32(float x) {
    uint32_t r;
    asm("cvt.rna.tf32.f32 %0, %1;" : "=r"(r) : "f"(x));
    return r;
}

#define MMA_TF32(c, a0, a1, a2, a3, b0, b1)                                          \
    asm volatile(                                                                    \
        "mma.sync.aligned.m16n8k8.row.col.f32.tf32.tf32.f32 "                        \
        "{%0,%1,%2,%3},{%4,%5,%6,%7},{%8,%9},{%0,%1,%2,%3};"                         \
        : "+f"(c[0]), "+f"(c[1]), "+f"(c[2]), "+f"(c[3])                             \
        : "r"(a0), "r"(a1), "r"(a2), "r"(a3), "r"(b0), "r"(b1));

// ---------------- counting sort by src>>1 + degree counts ----------------
__global__ void khist(const int* __restrict__ ei) {
    int e = blockIdx.x * blockDim.x + threadIdx.x;
    if (e >= NE) return;
    int s = ei[e], d = ei[NE + e];
    atomicAdd(&g_hist[s >> 1], 1u);
    if ((s >> 1) != (d >> 1)) atomicAdd(&g_cnt2[d >> 1], 1.f);
    if ((s >> 2) != (d >> 2)) atomicAdd(&g_cnt3[d >> 2], 1.f);
}

__global__ void kscan() {  // one block, 1024 threads, 64 bins each
    __shared__ unsigned sdata[1024];
    int t = threadIdx.x;
    int base = t * 64;
    unsigned s = 0;
#pragma unroll
    for (int i = 0; i < 64; i++) s += g_hist[base + i];
    sdata[t] = s;
    __syncthreads();
    for (int o = 1; o < 1024; o <<= 1) {
        unsigned v = (t >= o) ? sdata[t - o] : 0u;
        __syncthreads();
        sdata[t] += v;
        __syncthreads();
    }
    unsigned run = sdata[t] - s;  // exclusive prefix
#pragma unroll
    for (int i = 0; i < 64; i++) {
        unsigned h = g_hist[base + i];
        g_offs[base + i] = run;
        run += h;
    }
}

__global__ void kscatter(const int* __restrict__ ei) {
    int e = blockIdx.x * blockDim.x + threadIdx.x;
    if (e >= NE) return;
    int s = ei[e], d = ei[NE + e];
    unsigned p = atomicAdd(&g_offs[s >> 1], 1u);
    g_ssort[p] = s;
    g_dsort[p] = d;
}

// ---------------- pooled positions (pure function of pos) ----------------
__global__ void kpoolpos(const float* __restrict__ pos) {
    int n = blockIdx.x * blockDim.x + threadIdx.x;
    if (n >= N2) return;
    float2 a = *(const float2*)(pos + 4 * n);
    float2 b = *(const float2*)(pos + 4 * n + 2);
    *(float2*)(g_pos2 + 2 * n) = make_float2(0.5f * (a.x + b.x), 0.5f * (a.y + b.y));
    if (n < N3) {
        float2 c = *(const float2*)(pos + 8 * n);
        float2 d = *(const float2*)(pos + 8 * n + 2);
        float2 e = *(const float2*)(pos + 8 * n + 4);
        float2 f = *(const float2*)(pos + 8 * n + 6);
        *(float2*)(g_pos3 + 2 * n) =
            make_float2(0.25f * (c.x + d.x + e.x + f.x), 0.25f * (c.y + d.y + e.y + f.y));
    }
}

// ---------------- fused max |pos[dst]-pos[src]| for both pooled levels ----------------
__global__ void kmaxcart2() {
    int i = blockIdx.x * blockDim.x + threadIdx.x;
    int stride = gridDim.x * blockDim.x;
    float m2 = 0.f, m3 = 0.f;
    for (int e = i; e < NE; e += stride) {
        int s = g_ssort[e], d = g_dsort[e];
        int s2 = s >> 1, d2 = d >> 1, s3 = s >> 2, d3 = d >> 2;
        m2 = fmaxf(m2, fmaxf(fabsf(g_pos2[2 * d2] - g_pos2[2 * s2]),
                             fabsf(g_pos2[2 * d2 + 1] - g_pos2[2 * s2 + 1])));
        m3 = fmaxf(m3, fmaxf(fabsf(g_pos3[2 * d3] - g_pos3[2 * s3]),
                             fabsf(g_pos3[2 * d3 + 1] - g_pos3[2 * s3 + 1])));
    }
#pragma unroll
    for (int o = 16; o; o >>= 1) {
        m2 = fmaxf(m2, __shfl_xor_sync(0xffffffffu, m2, o));
        m3 = fmaxf(m3, __shfl_xor_sync(0xffffffffu, m3, o));
    }
    if ((threadIdx.x & 31) == 0) {
        atomicMax(&g_maxbits[0], __float_as_uint(m2));
        atomicMax(&g_maxbits[1], __float_as_uint(m3));
    }
}

// ---------------- layer 1 edge kernel: S[d,k] += g_k * x[src], 2 edges/warp ----------------
__global__ void kedge1(const int* __restrict__ ei, const float* __restrict__ ea,
                       const float* __restrict__ x, const float* __restrict__ mu,
                       const float* __restrict__ sigma) {
    __shared__ float sMu[NK * 2], sInv[NK * 2];
    int t = threadIdx.x;
    if (t < NK * 2) { sMu[t] = mu[t]; float s = sigma[t]; sInv[t] = 1.f / (EPSR + s * s); }
    __syncthreads();
    int w = (blockIdx.x * blockDim.x + t) >> 5;
    int lane = t & 31;
    int e0 = 2 * w;
    if (e0 >= NE) return;
    float muX = 0.f, muY = 0.f, ivX = 0.f, ivY = 0.f;
    if (lane < NK) { muX = sMu[2 * lane]; muY = sMu[2 * lane + 1]; ivX = sInv[2 * lane]; ivY = sInv[2 * lane + 1]; }
    int s0 = ei[e0], d0 = ei[NE + e0];
    int s1 = ei[e0 + 1], d1 = ei[NE + e0 + 1];
    float2 ea0 = *(const float2*)(ea + 2 * e0);
    float2 ea1 = *(const float2*)(ea + 2 * e0 + 2);
    float x0 = __ldg(&x[s0]), x1 = __ldg(&x[s1]);
    bool v0 = (s0 != d0), v1 = (s1 != d1);
    float g0 = 0.f, g1 = 0.f;
    if (lane < NK) {
        float dx0 = ea0.x - muX, dy0 = ea0.y - muY;
        float dx1 = ea1.x - muX, dy1 = ea1.y - muY;
        g0 = __expf(-0.5f * (dx0 * dx0 * ivX + dy0 * dy0 * ivY)) * x0;
        g1 = __expf(-0.5f * (dx1 * dx1 * ivX + dy1 * dy1 * ivY)) * x1;
    } else if (lane == NK) {
        g0 = 1.f; g1 = 1.f;
    }
    float a0 = __shfl_sync(0xffffffffu, g0, 2 * lane);
    float b0 = __shfl_sync(0xffffffffu, g0, 2 * lane + 1);
    float a1 = __shfl_sync(0xffffffffu, g1, 2 * lane);
    float b1 = __shfl_sync(0xffffffffu, g1, 2 * lane + 1);
    if (lane < 13) {
        if (v0) atomicAdd((float2*)&g_h1[(size_t)d0 * 32 + 2 * lane], make_float2(a0, b0));
        if (v1) atomicAdd((float2*)&g_h1[(size_t)d1 * 32 + 2 * lane], make_float2(a1, b1));
    }
}

// ---------------- fused layer1 node + pool: h2in[n] = max(elu(row(2n)), elu(row(2n+1))) -----
__global__ void knp1(const float* __restrict__ x, const float* __restrict__ W1,
                     const float* __restrict__ root, const float* __restrict__ b) {
    __shared__ float sW[NK * 32];
    int t = threadIdx.x;
    for (int i = t; i < NK * 32; i += blockDim.x) sW[i] = W1[i];
    __syncthreads();
    int n = (blockIdx.x * blockDim.x + t) >> 5;  // pair index
    int lane = t & 31;
    if (n >= N2) return;
    const float* row0 = &g_h1[(size_t)(2 * n) * 32];
    const float* row1 = row0 + 32;
    float acc0 = 0.f, acc1 = 0.f;
#pragma unroll
    for (int k = 0; k < NK; k++) {
        float w = sW[k * 32 + lane];
        acc0 += row0[k] * w;
        acc1 += row1[k] * w;
    }
    float rt = root[lane], bb = b[lane];
    float v0 = acc0 / fmaxf(row0[NK], 1.f) + x[2 * n] * rt + bb;
    float v1 = acc1 / fmaxf(row1[NK], 1.f) + x[2 * n + 1] * rt + bb;
    v0 = v0 > 0.f ? v0 : __expf(v0) - 1.f;
    v1 = v1 > 0.f ? v1 : __expf(v1) - 1.f;
    g_h2in[(size_t)n * 32 + lane] = fmaxf(v0, v1);
}

// ---------------- per-node Y precompute: tensor cores (tf32 2-term split) ----------------
template <int CIN>
__global__ void kgemmY(const float* __restrict__ H, const float* __restrict__ W,
                       float* __restrict__ Y) {
    constexpr int CINP = CIN + 1;
    __shared__ float sA[64 * CINP];
    __shared__ float sB[CIN * 68];
    int t = threadIdx.x;  // 128
    int n0 = blockIdx.x * 64;
    for (int i = t; i < 64 * CIN; i += 128) {
        int r = i / CIN, c = i % CIN;
        sA[r * CINP + c] = H[(size_t)(n0 + r) * CIN + c];
    }
    int warp = t >> 5, lane = t & 31, g = lane >> 2, tig = lane & 3;
    int wrow = warp * 16;
    constexpr int KT = CIN / 8;
    for (int kb = 0; kb < NK; kb++) {
        __syncthreads();
        for (int i = t; i < CIN * 64; i += 128) {
            int r = i >> 6, c = i & 63;
            sB[r * 68 + c] = W[((size_t)kb * CIN + r) * 64 + c];
        }
        __syncthreads();
        float acc[8][4] = {};
#pragma unroll
        for (int kt = 0; kt < KT; kt++) {
            float fa0 = sA[(wrow + g) * CINP + kt * 8 + tig];
            float fa1 = sA[(wrow + g + 8) * CINP + kt * 8 + tig];
            float fa2 = sA[(wrow + g) * CINP + kt * 8 + tig + 4];
            float fa3 = sA[(wrow + g + 8) * CINP + kt * 8 + tig + 4];
            uint32_t ah0 = f2tf32(fa0), ah1 = f2tf32(fa1), ah2 = f2tf32(fa2), ah3 = f2tf32(fa3);
            uint32_t al0 = f2tf32(fa0 - __uint_as_float(ah0));
            uint32_t al1 = f2tf32(fa1 - __uint_as_float(ah1));
            uint32_t al2 = f2tf32(fa2 - __uint_as_float(ah2));
            uint32_t al3 = f2tf32(fa3 - __uint_as_float(ah3));
#pragma unroll
            for (int nt = 0; nt < 8; nt++) {
                float fb0 = sB[(kt * 8 + tig) * 68 + nt * 8 + g];
                float fb1 = sB[(kt * 8 + tig + 4) * 68 + nt * 8 + g];
                uint32_t bh0 = f2tf32(fb0), bh1 = f2tf32(fb1);
                uint32_t bl0 = f2tf32(fb0 - __uint_as_float(bh0));
                uint32_t bl1 = f2tf32(fb1 - __uint_as_float(bh1));
                MMA_TF32(acc[nt], ah0, ah1, ah2, ah3, bh0, bh1);
                MMA_TF32(acc[nt], ah0, ah1, ah2, ah3, bl0, bl1);
                MMA_TF32(acc[nt], al0, al1, al2, al3, bh0, bh1);
            }
        }
#pragma unroll
        for (int nt = 0; nt < 8; nt++) {
            size_t base = (size_t)(n0 + wrow + g) * 1600 + kb * 64 + nt * 8 + 2 * tig;
            *(float2*)&Y[base] = make_float2(acc[nt][0], acc[nt][1]);
            *(float2*)&Y[base + (size_t)8 * 1600] = make_float2(acc[nt][2], acc[nt][3]);
        }
    }
}

// ---------------- layers 2/3: warp per SRC node, Y row in registers, 2-edge unroll ----------
template <int SHIFT>
__global__ void __launch_bounds__(256) kedgeY(
        const float* __restrict__ pos,
        const float* __restrict__ mu, const float* __restrict__ sigma,
        const float* __restrict__ Y, float* __restrict__ agg,
        const unsigned* __restrict__ maxbits, int nnodes) {
    __shared__ float sMu[NK * 2], sInv[NK * 2];
    int t = threadIdx.x;
    if (t < NK * 2) { sMu[t] = mu[t]; float sv = sigma[t]; sInv[t] = 1.f / (EPSR + sv * sv); }
    __syncthreads();
    int s = (blockIdx.x * blockDim.x + t) >> 5;
    int lane = t & 31;
    if (s >= nnodes) return;
    int start, end;
    if (SHIFT == 1) {
        start = (int)(g_offs[s] - g_hist[s]);
        end = (int)g_offs[s];
    } else {
        start = (int)(g_offs[2 * s] - g_hist[2 * s]);
        end = (int)g_offs[2 * s + 1];
    }
    if (start >= end) return;
    float2 Yv[NK];
    const float* Yr = Y + (size_t)s * 1600;
#pragma unroll
    for (int k = 0; k < NK; k++) Yv[k] = __ldg((const float2*)(Yr + k * 64 + 2 * lane));
    float2 ps = *(const float2*)(pos + 2 * s);
    float scale = 0.5f / fmaxf(__uint_as_float(*maxbits), 1e-12f);
    float muX = 0.f, muY = 0.f, ivX = 0.f, ivY = 0.f;
    if (lane < NK) { muX = sMu[2 * lane]; muY = sMu[2 * lane + 1]; ivX = sInv[2 * lane]; ivY = sInv[2 * lane + 1]; }

    int e = start;
    if ((end - start) & 1) {
        int d = __ldg(&g_dsort[e]) >> SHIFT;
        e++;
        if (d != s) {
            float2 pd = __ldg((const float2*)(pos + 2 * d));
            float g = 0.f;
            if (lane < NK) {
                float px = (pd.x - ps.x) * scale + 0.5f - muX;
                float py = (pd.y - ps.y) * scale + 0.5f - muY;
                g = __expf(-0.5f * (px * px * ivX + py * py * ivY));
            }
            float ax = 0.f, ay = 0.f;
#pragma unroll
            for (int k = 0; k < NK; k++) {
                float gk = __shfl_sync(0xffffffffu, g, k);
                ax += gk * Yv[k].x;
                ay += gk * Yv[k].y;
            }
            atomicAdd((float2*)&agg[(size_t)d * 64 + 2 * lane], make_float2(ax, ay));
        }
    }
    for (; e < end; e += 2) {
        int d0 = __ldg(&g_dsort[e]) >> SHIFT;
        int d1 = __ldg(&g_dsort[e + 1]) >> SHIFT;
        float2 pd0 = __ldg((const float2*)(pos + 2 * d0));
        float2 pd1 = __ldg((const float2*)(pos + 2 * d1));
        bool v0 = (d0 != s), v1 = (d1 != s);
        float g0 = 0.f, g1 = 0.f;
        if (lane < NK) {
            float px0 = (pd0.x - ps.x) * scale + 0.5f - muX;
            float py0 = (pd0.y - ps.y) * scale + 0.5f - muY;
            float px1 = (pd1.x - ps.x) * scale + 0.5f - muX;
            float py1 = (pd1.y - ps.y) * scale + 0.5f - muY;
            g0 = v0 ? __expf(-0.5f * (px0 * px0 * ivX + py0 * py0 * ivY)) : 0.f;
            g1 = v1 ? __expf(-0.5f * (px1 * px1 * ivX + py1 * py1 * ivY)) : 0.f;
        }
        float ax0 = 0.f, ay0 = 0.f, ax1 = 0.f, ay1 = 0.f;
#pragma unroll
        for (int k = 0; k < NK; k++) {
            float gk0 = __shfl_sync(0xffffffffu, g0, k);
            float gk1 = __shfl_sync(0xffffffffu, g1, k);
            ax0 += gk0 * Yv[k].x;
            ay0 += gk0 * Yv[k].y;
            ax1 += gk1 * Yv[k].x;
            ay1 += gk1 * Yv[k].y;
        }
        if (v0) atomicAdd((float2*)&agg[(size_t)d0 * 64 + 2 * lane], make_float2(ax0, ay0));
        if (v1) atomicAdd((float2*)&agg[(size_t)d1 * 64 + 2 * lane], make_float2(ax1, ay1));
    }
}

// ---------------- fused layer2 node + pool: h3in = max over pair of relu(node out) ----------
__global__ void knp2(const float* __restrict__ root, const float* __restrict__ b) {
    int idx = blockIdx.x * blockDim.x + threadIdx.x;
    if (idx >= N3 * 64) return;
    int n = idx >> 6, c = idx & 63;
    float r0 = b[c], r1 = r0;
    const float* h0 = &g_h2in[(size_t)(2 * n) * 32];
    const float* h1 = h0 + 32;
#pragma unroll
    for (int i = 0; i < 32; i++) {
        float w = root[i * 64 + c];
        r0 += h0[i] * w;
        r1 += h1[i] * w;
    }
    float v0 = g_agg2[(size_t)(2 * n) * 64 + c] / fmaxf(g_cnt2[2 * n], 1.f) + r0;
    float v1 = g_agg2[(size_t)(2 * n + 1) * 64 + c] / fmaxf(g_cnt2[2 * n + 1], 1.f) + r1;
    g_h3in[idx] = fmaxf(fmaxf(v0, 0.f), fmaxf(v1, 0.f));
}

// ---------------- layer 3 node (ELU, in place on agg3) ----------------
__global__ void knode3(const float* __restrict__ root, const float* __restrict__ b) {
    int idx = blockIdx.x * blockDim.x + threadIdx.x;
    if (idx >= N3 * 64) return;
    int n = idx >> 6, c = idx & 63;
    float r = b[c];
    const float* hr = &g_h3in[(size_t)n * 64];
#pragma unroll
    for (int i = 0; i < 64; i++) r += hr[i] * root[i * 64 + c];
    float v = g_agg3[idx] / fmaxf(g_cnt3[n], 1.f) + r;
    g_agg3[idx] = v > 0.f ? v : __expf(v) - 1.f;
}

__global__ void kbatchpool() {
    __shared__ float sred[256];
    int b = blockIdx.x, t = threadIdx.x;
    int c = t & 63, part = t >> 6;
    float s = 0.f;
    for (int j = part; j < 512; j += 4) s += g_agg3[(size_t)(b * 512 + j) * 64 + c];
    sred[t] = s;
    __syncthreads();
    if (part == 0)
        g_pooled[b * 64 + c] = (sred[c] + sred[64 + c] + sred[128 + c] + sred[192 + c]) * (1.f / 512.f);
}

__global__ void khead(const float* __restrict__ fw1, const float* __restrict__ fb1,
                      const float* __restrict__ fw2, const float* __restrict__ fb2,
                      float* __restrict__ out) {
    int b = blockIdx.x;
    int t = threadIdx.x;
    __shared__ float sp[64], sz[128], so[10], lse;
    if (t < 64) sp[t] = g_pooled[b * 64 + t];
    __syncthreads();
    float acc = fb1[t];
    for (int i = 0; i < 64; i++) acc += sp[i] * fw1[i * 128 + t];
    sz[t] = acc > 0.f ? acc : expf(acc) - 1.f;
    __syncthreads();
    if (t < 10) {
        float o = fb2[t];
        for (int j = 0; j < 128; j++) o += sz[j] * fw2[j * 10 + t];
        so[t] = o;
    }
    __syncthreads();
    if (t == 0) {
        float m = so[0];
        for (int i = 1; i < 10; i++) m = fmaxf(m, so[i]);
        float s = 0.f;
        for (int i = 0; i < 10; i++) s += expf(so[i] - m);
        lse = m + logf(s);
    }
    __syncthreads();
    if (t < 10) out[b * 10 + t] = so[t] - lse;
}

// ---------------- launch ----------------
extern "C" void kernel_launch(void* const* d_in, const int* in_sizes, int n_in,
                              void* d_out, int out_size) {
    const float* x   = (const float*)d_in[0];
    const int*   ei  = (const int*)d_in[1];
    const float* ea  = (const float*)d_in[2];
    const float* pos = (const float*)d_in[3];
    const float* mu1 = (const float*)d_in[5];
    const float* sg1 = (const float*)d_in[6];
    const float* W1  = (const float*)d_in[7];
    const float* r1  = (const float*)d_in[8];
    const float* b1  = (const float*)d_in[9];
    const float* mu2 = (const float*)d_in[10];
    const float* sg2 = (const float*)d_in[11];
    const float* W2  = (const float*)d_in[12];
    const float* r2  = (const float*)d_in[13];
    const float* b2  = (const float*)d_in[14];
    const float* mu3 = (const float*)d_in[15];
    const float* sg3 = (const float*)d_in[16];
    const float* W3  = (const float*)d_in[17];
    const float* r3  = (const float*)d_in[18];
    const float* b3  = (const float*)d_in[19];
    const float* fw1 = (const float*)d_in[20];
    const float* fb1 = (const float*)d_in[21];
    const float* fw2 = (const float*)d_in[22];
    const float* fb2 = (const float*)d_in[23];
    float* out = (float*)d_out;

    void *p_h1, *p_h2, *p_Y2, *p_a2, *p_c2, *p_h3, *p_Y3, *p_a3, *p_c3, *p_mb, *p_p2, *p_p3, *p_hist;
    cudaGetSymbolAddress(&p_h1, g_h1);
    cudaGetSymbolAddress(&p_h2, g_h2in);
    cudaGetSymbolAddress(&p_Y2, g_Y2);
    cudaGetSymbolAddress(&p_a2, g_agg2);
    cudaGetSymbolAddress(&p_c2, g_cnt2);
    cudaGetSymbolAddress(&p_h3, g_h3in);
    cudaGetSymbolAddress(&p_Y3, g_Y3);
    cudaGetSymbolAddress(&p_a3, g_agg3);
    cudaGetSymbolAddress(&p_c3, g_cnt3);
    cudaGetSymbolAddress(&p_mb, g_maxbits);
    cudaGetSymbolAddress(&p_p2, g_pos2);
    cudaGetSymbolAddress(&p_p3, g_pos3);
    cudaGetSymbolAddress(&p_hist, g_hist);

    cudaMemsetAsync(p_h1, 0, (size_t)N1 * 32 * 4);
    cudaMemsetAsync(p_a2, 0, (size_t)N2 * 64 * 4);
    cudaMemsetAsync(p_c2, 0, (size_t)N2 * 4);
    cudaMemsetAsync(p_a3, 0, (size_t)N3 * 64 * 4);
    cudaMemsetAsync(p_c3, 0, (size_t)N3 * 4);
    cudaMemsetAsync(p_mb, 0, 2 * 4);
    cudaMemsetAsync(p_hist, 0, (size_t)N2 * 4);

    // counting sort of edges by src>>1 (serves layers 2 and 3) + degree counts
    khist<<<NE / 256, 256>>>(ei);
    kscan<<<1, 1024>>>();
    kscatter<<<NE / 256, 256>>>(ei);

    // pooled positions + fused max-cart (independent of h)
    kpoolpos<<<N2 / 256, 256>>>(pos);
    kmaxcart2<<<1024, 256>>>();

    // layer 1
    kedge1<<<NE * 32 / 2 / 256, 256>>>(ei, ea, x, mu1, sg1);
    knp1<<<N2 * 32 / 256, 256>>>(x, W1, r1, b1);

    // layer 2
    kgemmY<32><<<N2 / 64, 128>>>((const float*)p_h2, W2, (float*)p_Y2);
    kedgeY<1><<<N2 * 32 / 256, 256>>>((const float*)p_p2, mu2, sg2,
                                      (const float*)p_Y2, (float*)p_a2,
                                      (const unsigned*)p_mb, N2);
    knp2<<<N3 * 64 / 256, 256>>>(r2, b2);

    // layer 3
    kgemmY<64><<<N3 / 64, 128>>>((const float*)p_h3, W3, (float*)p_Y3);
    kedgeY<2><<<N3 * 32 / 256, 256>>>((const float*)p_p3, mu3, sg3,
                                      (const float*)p_Y3, (float*)p_a3,
                                      ((const unsigned*)p_mb) + 1, N3);
    knode3<<<N3 * 64 / 256, 256>>>(r3, b3);

    // readout
    kbatchpool<<<NB, 256>>>();
    khead<<<NB, 128>>>(fw1, fb1, fw2, fb2, out);
}